// round 16
// baseline (speedup 1.0000x reference)
#include <cuda_runtime.h>
#include <cuda_bf16.h>
#include <math.h>

#define NB 128

// ---------------- scratch ----------------
__device__ float g_t1[(size_t)NB*8*128*128];
__device__ float g_ds[(size_t)NB*32*64*64];
__device__ float g_t3[(size_t)NB*4*32*32];
__device__ float g_r1[(size_t)NB*64*64*64];
__device__ float g_r2[(size_t)NB*20*64*64];
__device__ float g_u1[(size_t)NB*30*64*64];
__device__ float g_part[2*64*1024];
__device__ float g_scale[64];
__device__ float g_shift[64];
__device__ float g_contrib[NB*9*64];
__device__ float g_pwblur[NB*20];

typedef unsigned long long u64;
__device__ __align__(16) u64 g_wp_r1[64*148];
__device__ __align__(16) u64 g_wp_r2[24*292];
__device__ __align__(16) u64 g_wp_u1[32*100];
__device__ __align__(16) u64 g_wp_c2[32*100];
__device__ __align__(16) u64 g_wp_c1[8*20];
__device__ __align__(16) u64 g_wp_c3[8*148];

// ---------------- helpers ----------------
static __device__ __forceinline__ u64 pack2(float x, float y) {
    u64 r; asm("mov.b64 %0, {%1, %2};" : "=l"(r) : "f"(x), "f"(y)); return r;
}
static __device__ __forceinline__ u64 bcast2(float x) { return pack2(x, x); }
static __device__ __forceinline__ void fma2(u64& d, u64 a, u64 b) {
    asm("fma.rn.f32x2 %0, %1, %2, %0;" : "+l"(d) : "l"(a), "l"(b));
}
static __device__ __forceinline__ float2 unpack2(u64 v) {
    float2 r; asm("mov.b64 {%0, %1}, %2;" : "=f"(r.x), "=f"(r.y) : "l"(v)); return r;
}
static __device__ __forceinline__ unsigned to_tf32(float v) {
    unsigned u; asm("cvt.rna.tf32.f32 %0, %1;" : "=r"(u) : "f"(v)); return u;
}
static __device__ __forceinline__ u64 packtf2(float x, float y) {
    return (u64)to_tf32(x) | ((u64)to_tf32(y) << 32);
}
static __device__ __forceinline__ void mma_tf32(
    float* acc, unsigned a0, unsigned a1, unsigned a2, unsigned a3,
    unsigned b0, unsigned b1)
{
    asm volatile(
      "mma.sync.aligned.m16n8k8.row.col.f32.tf32.tf32.f32 "
      "{%0,%1,%2,%3}, {%4,%5,%6,%7}, {%8,%9}, {%0,%1,%2,%3};"
      : "+f"(acc[0]), "+f"(acc[1]), "+f"(acc[2]), "+f"(acc[3])
      : "r"(a0), "r"(a1), "r"(a2), "r"(a3), "r"(b0), "r"(b1));
}

__host__ __device__ constexpr int ceil8i(int x) { return (x + 7) & ~7; }
__host__ __device__ constexpr int pad64(int x) { return x + ((4 - (x & 15)) + 16) % 16; }

// =====================================================================
// Merged weight pre-pack.
// =====================================================================
template<int CIN,int CINC,int WCIN,int CIOFF,int COUT,int COUTP>
static __device__ __forceinline__ u64 pack3_elem(const float* __restrict__ w, int idx)
{
    constexpr int KC  = CINC*9;
    constexpr int KCP = ceil8i(KC);
    constexpr int KP  = (CIN/CINC)*KCP;
    constexpr int P64 = pad64(KP/2);
    int co = idx / P64; int j = idx - co*P64;
    u64 val = 0;
    if (j < (KP/8)*4) {
        int kgrp = j >> 2, tg = j & 3;
        int k0 = kgrp*8 + tg, k1 = k0 + 4;
        int chunk = k0 / KCP;
        int kin0 = k0 - chunk*KCP, kin1 = k1 - chunk*KCP;
        float v0 = 0.f, v1 = 0.f;
        if (co < COUT && kin0 < KC)
            v0 = w[((size_t)co*WCIN + CIOFF + chunk*CINC + kin0/9)*9 + kin0%9];
        if (co < COUT && kin1 < KC)
            v1 = w[((size_t)co*WCIN + CIOFF + chunk*CINC + kin1/9)*9 + kin1%9];
        val = packtf2(v0, v1);
    }
    return val;
}

__global__ void packall_k(const float* __restrict__ r1w, const float* __restrict__ r2w,
                          const float* __restrict__ u1w, const float* __restrict__ c2w,
                          const float* __restrict__ c1w, const float* __restrict__ c3w,
                          u64* __restrict__ wr1, u64* __restrict__ wr2,
                          u64* __restrict__ wu1, u64* __restrict__ wc2,
                          u64* __restrict__ wc1, u64* __restrict__ wc3)
{
    int idx = blockIdx.x*blockDim.x + threadIdx.x;
    if (idx < 64*148) {
        wr1[idx] = pack3_elem<32,16,48,16,64,64>(r1w, idx);
    } else if (idx < 64*148 + 24*292) {
        int i = idx - 64*148;
        wr2[i] = pack3_elem<64,16,64,0,20,24>(r2w, i);
    } else if (idx < 64*148 + 24*292 + 32*100) {
        int i = idx - (64*148 + 24*292);
        wu1[i] = pack3_elem<20,20,20,0,30,32>(u1w, i);
    } else if (idx < 64*148 + 24*292 + 2*32*100) {
        int i = idx - (64*148 + 24*292 + 32*100);
        int co = i / 100; int j = i - co*100;
        int kgrp = j >> 2, tg = j & 3;
        int k0 = kgrp*8 + tg;
        wc2[i] = packtf2(c2w[(size_t)co*200 + k0], c2w[(size_t)co*200 + k0 + 4]);
    } else if (idx < 64*148 + 24*292 + 2*32*100 + 8*20) {
        int i = idx - (64*148 + 24*292 + 2*32*100);
        wc1[i] = pack3_elem<1,1,1,0,8,8>(c1w, i);
    } else if (idx < 64*148 + 24*292 + 2*32*100 + 8*20 + 8*148) {
        int i = idx - (64*148 + 24*292 + 2*32*100 + 8*20);
        wc3[i] = pack3_elem<32,8,32,0,4,8>(c3w, i);
    }
}

// =====================================================================
// Tensor-core 3x3 s1 p1 conv, 8 output rows per block, 1024 threads.
// Row-based staging: one warp per (ci, row), addressing amortized.
// =====================================================================
template<int CIN,int CINC,int WCIN,int CIOFF,int COUT,int COUTP,bool RELU,bool BNIN,bool CONTRIB,bool STATS>
__global__ __launch_bounds__(1024) void tc_conv3_k(
    const float* __restrict__ in, const u64* __restrict__ wp,
    const float* __restrict__ bias, const float* __restrict__ bnsc,
    const float* __restrict__ bnsh, const float* __restrict__ contrib,
    float* __restrict__ out, float* __restrict__ bnpart)
{
    constexpr int CHUNKS = CIN / CINC;
    static_assert(CIN % CINC == 0 && COUTP % 8 == 0, "");
    constexpr int KC   = CINC*9;
    constexpr int KCP  = ceil8i(KC);
    constexpr int KP   = CHUNKS*KCP;
    constexpr int P64  = pad64(KP/2);
    constexpr int IN_S = (CINC*10*68 + 3) & ~3;
    constexpr int NT   = COUTP/8;
    constexpr int NKS  = KCP/8;
    extern __shared__ unsigned smu[];
    unsigned* in_s = smu;
    u64*  w2_s = (u64*)(smu + IN_S);
    int2* lut_s = (int2*)(w2_s + (size_t)COUTP*P64);
    float* st_s = (float*)(lut_s + NKS*4);

    const int n   = blockIdx.y;
    const int oy0 = blockIdx.x * 8;
    const int tid = threadIdx.x;
    const int lane = tid & 31;
    const int mt  = tid >> 5;          // 0..31
    const int tg  = lane & 3;
    const int gid = lane >> 2;

    {
        ulonglong2* d = (ulonglong2*)w2_s;
        const ulonglong2* s = (const ulonglong2*)wp;
        for (int i = tid; i < COUTP*P64/2; i += 1024) d[i] = s[i];
    }
    for (int j = tid; j < NKS*4; j += 1024) {
        int ks = j >> 2, tg_ = j & 3;
        int k0 = ks*8 + tg_, k1 = k0 + 4;
        int t0 = 0, t1 = 0;
        if (k0 < KC) { int c = k0/9, tp = k0%9; t0 = (c*10 + tp/3)*68 + tp%3; }
        if (k1 < KC) { int c = k1/9, tp = k1%9; t1 = (c*10 + tp/3)*68 + tp%3; }
        lut_s[j] = make_int2(t0, t1);
    }

    float acc[NT][4];
    #pragma unroll
    for (int nt = 0; nt < NT; nt++)
        #pragma unroll
        for (int e = 0; e < 4; e++) acc[nt][e] = 0.f;

    const int base = (mt >> 2)*68 + (mt & 3)*16 + gid;

    for (int chunk = 0; chunk < CHUNKS; chunk++) {
        __syncthreads();
        const int ci0 = chunk*CINC;
        // row-based staging: warp per (ci, ry)
        for (int r = mt; r < CINC*10; r += 32) {
            int ci = r / 10, ry = r - ci*10;
            int iy = oy0 - 1 + ry;
            unsigned* dst = in_s + r*68;
            if ((unsigned)iy < 64u) {
                const float* src = in + ((size_t)n*CIN + ci0 + ci)*4096 + iy*64;
                float sc = 0.f, sh = 0.f;
                if (BNIN) { sc = bnsc[ci0+ci]; sh = bnsh[ci0+ci]; }
                for (int cx = lane; cx < 66; cx += 32) {
                    int ix = cx - 1;
                    float val = 0.f;
                    if ((unsigned)ix < 64u) {
                        val = src[ix];
                        if (BNIN) val = fmaxf(fmaf(val, sc, sh), 0.f);
                    }
                    dst[cx] = to_tf32(val);
                }
            } else {
                for (int cx = lane; cx < 66; cx += 32) dst[cx] = 0u;
            }
        }
        __syncthreads();

        const u64* wc = w2_s + chunk*NKS*4 + tg + (size_t)gid*P64;
        #pragma unroll
        for (int ks = 0; ks < NKS; ks++) {
            int2 tt = lut_s[ks*4 + tg];
            unsigned a0 = in_s[tt.x + base];
            unsigned a1 = in_s[tt.x + base + 8];
            unsigned a2 = in_s[tt.y + base];
            unsigned a3 = in_s[tt.y + base + 8];
            #pragma unroll
            for (int nt = 0; nt < NT; nt++) {
                u64 bb = wc[ks*4 + (size_t)(nt*8)*P64];
                mma_tf32(acc[nt], a0, a1, a2, a3, (unsigned)bb, (unsigned)(bb >> 32));
            }
        }
    }

    const int oy = oy0 + (mt >> 2);
    const int x0 = (mt & 3)*16;
    const int vy = (oy == 0) ? 0 : ((oy == 63) ? 2 : 1);
    float sacc[NT][2], s2acc[NT][2];
    if (STATS) {
        #pragma unroll
        for (int nt = 0; nt < NT; nt++) { sacc[nt][0]=sacc[nt][1]=0.f; s2acc[nt][0]=s2acc[nt][1]=0.f; }
    }
    #pragma unroll
    for (int half = 0; half < 2; half++) {
        int x = x0 + gid + half*8;
        int vx = (x == 0) ? 0 : ((x == 63) ? 2 : 1);
        const float* cp = CONTRIB ? &contrib[((size_t)n*9 + vy*3 + vx)*64] : nullptr;
        float* op = out + (size_t)n*COUT*4096 + (size_t)oy*64 + x;
        #pragma unroll
        for (int nt = 0; nt < NT; nt++) {
            #pragma unroll
            for (int e = 0; e < 2; e++) {
                int co = nt*8 + 2*tg + e;
                float bv = (co < COUT) ? bias[co] : 0.f;
                float v = acc[nt][half*2 + e] + bv;
                if (CONTRIB) v += (co < COUT) ? cp[co] : 0.f;
                if (RELU) v = fmaxf(v, 0.f);
                if (co < COUT) op[(size_t)co*4096] = v;
                if (STATS) { sacc[nt][e] += v; s2acc[nt][e] += v*v; }
            }
        }
    }
    if (STATS) {
        #pragma unroll
        for (int nt = 0; nt < NT; nt++) {
            #pragma unroll
            for (int e = 0; e < 2; e++) {
                float s = sacc[nt][e], s2 = s2acc[nt][e];
                s  += __shfl_xor_sync(0xffffffffu, s, 4);
                s2 += __shfl_xor_sync(0xffffffffu, s2, 4);
                s  += __shfl_xor_sync(0xffffffffu, s, 8);
                s2 += __shfl_xor_sync(0xffffffffu, s2, 8);
                s  += __shfl_xor_sync(0xffffffffu, s, 16);
                s2 += __shfl_xor_sync(0xffffffffu, s2, 16);
                if (gid == 0) {
                    int co = nt*8 + 2*tg + e;
                    st_s[(mt*COUTP + co)*2 + 0] = s;
                    st_s[(mt*COUTP + co)*2 + 1] = s2;
                }
            }
        }
        __syncthreads();
        if (tid < COUT) {
            float S = 0.f, S2 = 0.f;
            #pragma unroll
            for (int wq = 0; wq < 32; wq++) {
                S  += st_s[(wq*COUTP + tid)*2 + 0];
                S2 += st_s[(wq*COUTP + tid)*2 + 1];
            }
            int blk = blockIdx.y*gridDim.x + blockIdx.x;
            bnpart[(size_t)tid*1024 + blk] = S;
            bnpart[(size_t)COUT*1024 + (size_t)tid*1024 + blk] = S2;
        }
    }
}

// =====================================================================
// Tensor-core conv2: 8->32, k5, s2, p2, 128->64. Row-based staging.
// =====================================================================
__global__ __launch_bounds__(512) void tc_conv2_k(
    const float* __restrict__ in, const u64* __restrict__ wp,
    const float* __restrict__ bias, float* __restrict__ out)
{
    constexpr int IN_S = 8*11*132;
    extern __shared__ unsigned smu[];
    unsigned* in_s = smu;
    u64*  w2_s = (u64*)(smu + IN_S);
    int2* lut_s = (int2*)(w2_s + 32*100);

    const int n   = blockIdx.y;
    const int oy0 = blockIdx.x * 4;
    const int tid = threadIdx.x;
    const int lane = tid & 31;
    const int mt  = tid >> 5;
    const int tg  = lane & 3;
    const int gid = lane >> 2;

    {
        ulonglong2* d = (ulonglong2*)w2_s;
        const ulonglong2* s = (const ulonglong2*)wp;
        for (int i = tid; i < 32*100/2; i += 512) d[i] = s[i];
    }
    for (int j = tid; j < 100; j += 512) {
        int ks = j >> 2, tg_ = j & 3;
        int k0 = ks*8 + tg_, k1 = k0 + 4;
        int c0 = k0/25, r0 = k0%25, c1 = k1/25, r1 = k1%25;
        lut_s[j] = make_int2((c0*11 + r0/5)*132 + r0%5,
                             (c1*11 + r1/5)*132 + r1%5);
    }
    // row-based staging: warp per (ci, ry)
    for (int r = mt; r < 8*11; r += 16) {
        int ci = r / 11, ry = r - ci*11;
        int iy = 2*oy0 - 2 + ry;
        unsigned* dst = in_s + r*132;
        if ((unsigned)iy < 128u) {
            const float* src = in + ((size_t)n*8 + ci)*16384 + iy*128;
            for (int cx = lane; cx < 131; cx += 32) {
                int ix = cx - 2;
                float val = ((unsigned)ix < 128u) ? src[ix] : 0.f;
                dst[cx] = to_tf32(val);
            }
        } else {
            for (int cx = lane; cx < 131; cx += 32) dst[cx] = 0u;
        }
    }
    __syncthreads();

    float acc[4][4];
    #pragma unroll
    for (int nt = 0; nt < 4; nt++)
        #pragma unroll
        for (int e = 0; e < 4; e++) acc[nt][e] = 0.f;

    const int base = (mt >> 2)*264 + (mt & 3)*32 + 2*gid;
    const u64* wc = w2_s + tg + (size_t)gid*100;
    #pragma unroll
    for (int ks = 0; ks < 25; ks++) {
        int2 tt = lut_s[ks*4 + tg];
        unsigned a0 = in_s[tt.x + base];
        unsigned a1 = in_s[tt.x + base + 16];
        unsigned a2 = in_s[tt.y + base];
        unsigned a3 = in_s[tt.y + base + 16];
        #pragma unroll
        for (int nt = 0; nt < 4; nt++) {
            u64 bb = wc[ks*4 + (size_t)(nt*8)*100];
            mma_tf32(acc[nt], a0, a1, a2, a3, (unsigned)bb, (unsigned)(bb >> 32));
        }
    }

    const int oy = oy0 + (mt >> 2);
    const int x0 = (mt & 3)*16;
    #pragma unroll
    for (int half = 0; half < 2; half++) {
        int x = x0 + gid + half*8;
        float* op = out + (size_t)n*32*4096 + (size_t)oy*64 + x;
        #pragma unroll
        for (int nt = 0; nt < 4; nt++) {
            #pragma unroll
            for (int e = 0; e < 2; e++) {
                int co = nt*8 + 2*tg + e;
                float v = fmaxf(acc[nt][half*2 + e] + bias[co], 0.f);
                op[(size_t)co*4096] = v;
            }
        }
    }
}

// =====================================================================
// Tensor-core conv3: 32->4, k3, s2, p1, 64->32. Row-based staging.
// =====================================================================
__global__ __launch_bounds__(512) void tc_conv3s2_k(
    const float* __restrict__ in, const u64* __restrict__ wp,
    const float* __restrict__ bias, float* __restrict__ out)
{
    constexpr int CINC = 8, CHUNKS = 4;
    constexpr int KC = 72, NKS = 9;
    constexpr int P64 = pad64(288/2);    // 148
    constexpr int IN_S = (CINC*17*66 + 3) & ~3;
    extern __shared__ unsigned smu[];
    unsigned* in_s = smu;
    u64*  w2_s = (u64*)(smu + IN_S);
    int2* lut_s = (int2*)(w2_s + 8*P64);

    const int n   = blockIdx.y;
    const int oy0 = blockIdx.x * 8;
    const int tid = threadIdx.x;
    const int lane = tid & 31;
    const int mt  = tid >> 5;
    const int tg  = lane & 3;
    const int gid = lane >> 2;

    {
        ulonglong2* d = (ulonglong2*)w2_s;
        const ulonglong2* s = (const ulonglong2*)wp;
        for (int i = tid; i < 8*P64/2; i += 512) d[i] = s[i];
    }
    for (int j = tid; j < NKS*4; j += 512) {
        int ks = j >> 2, tg_ = j & 3;
        int k0 = ks*8 + tg_, k1 = k0 + 4;
        int t0 = 0, t1 = 0;
        if (k0 < KC) { int c = k0/9, tp = k0%9; t0 = (c*17 + tp/3)*66 + tp%3; }
        if (k1 < KC) { int c = k1/9, tp = k1%9; t1 = (c*17 + tp/3)*66 + tp%3; }
        lut_s[j] = make_int2(t0, t1);
    }

    float acc[4] = {0.f, 0.f, 0.f, 0.f};
    const int base = (mt >> 1)*2*66 + ((mt & 1)*16 + gid)*2;

    for (int chunk = 0; chunk < CHUNKS; chunk++) {
        __syncthreads();
        const int ci0 = chunk*CINC;
        for (int r = mt; r < CINC*17; r += 16) {
            int ci = r / 17, ry = r - ci*17;
            int iy = 2*oy0 - 1 + ry;
            unsigned* dst = in_s + r*66;
            if ((unsigned)iy < 64u) {
                const float* src = in + ((size_t)n*32 + ci0 + ci)*4096 + iy*64;
                for (int cx = lane; cx < 66; cx += 32) {
                    int ix = cx - 1;
                    float val = ((unsigned)ix < 64u) ? src[ix] : 0.f;
                    dst[cx] = to_tf32(val);
                }
            } else {
                for (int cx = lane; cx < 66; cx += 32) dst[cx] = 0u;
            }
        }
        __syncthreads();

        const u64* wc = w2_s + chunk*NKS*4 + tg + (size_t)gid*P64;
        #pragma unroll
        for (int ks = 0; ks < NKS; ks++) {
            int2 tt = lut_s[ks*4 + tg];
            unsigned a0 = in_s[tt.x + base];
            unsigned a1 = in_s[tt.x + base + 16];
            unsigned a2 = in_s[tt.y + base];
            unsigned a3 = in_s[tt.y + base + 16];
            u64 bb = wc[ks*4];
            mma_tf32(acc, a0, a1, a2, a3, (unsigned)bb, (unsigned)(bb >> 32));
        }
    }

    const int oy = oy0 + (mt >> 1);
    const int x0 = (mt & 1)*16;
    #pragma unroll
    for (int half = 0; half < 2; half++) {
        int x = x0 + gid + half*8;
        float* op = out + (size_t)n*4*1024 + (size_t)oy*32 + x;
        #pragma unroll
        for (int e = 0; e < 2; e++) {
            int co = 2*tg + e;
            if (co < 4)
                op[(size_t)co*1024] = acc[half*2 + e] + bias[co];
        }
    }
}

// =====================================================================
// Tensor-core conv1: 1->8, k3, s2, p1, 256->128.
// =====================================================================
__global__ __launch_bounds__(512) void tc_conv1_k(
    const float* __restrict__ in, const u64* __restrict__ wp,
    const float* __restrict__ bias, float* __restrict__ out)
{
    constexpr int P64 = 20;
    constexpr int IN_RAW = 5*258;
    constexpr int IN_S = (IN_RAW + 3) & ~3;
    extern __shared__ unsigned smu[];
    unsigned* in_s = smu;
    u64*  w2_s = (u64*)(smu + IN_S);
    int2* lut_s = (int2*)(w2_s + 8*20);

    const int n   = blockIdx.y;
    const int oy0 = blockIdx.x * 2;
    const int tid = threadIdx.x;
    const int lane = tid & 31;
    const int mt  = tid >> 5;
    const int tg  = lane & 3;
    const int gid = lane >> 2;

    if (tid < 80) {
        ((ulonglong2*)w2_s)[tid] = ((const ulonglong2*)wp)[tid];
    }
    if (tid < 8) {
        int ks = tid >> 2, tg_ = tid & 3;
        int k0 = ks*8 + tg_, k1 = k0 + 4;
        int t0 = (k0 < 9) ? (k0/3)*258 + k0%3 : 0;
        int t1 = (k1 < 9) ? (k1/3)*258 + k1%3 : 0;
        lut_s[tid] = make_int2(t0, t1);
    }
    // row-based staging: warp per row (5 rows)
    for (int r = mt; r < 5; r += 16) {
        int iy = 2*oy0 - 1 + r;
        unsigned* dst = in_s + r*258;
        if ((unsigned)iy < 256u) {
            const float* src = in + (size_t)n*65536 + iy*256;
            for (int cx = lane; cx < 258; cx += 32) {
                int ix = cx - 1;
                float val = ((unsigned)ix < 256u) ? src[ix] : 0.f;
                dst[cx] = to_tf32(val);
            }
        } else {
            for (int cx = lane; cx < 258; cx += 32) dst[cx] = 0u;
        }
    }
    __syncthreads();

    float acc[4] = {0.f, 0.f, 0.f, 0.f};
    const int base = (mt >> 3)*516 + ((mt & 7)*16 + gid)*2;
    #pragma unroll
    for (int ks = 0; ks < 2; ks++) {
        int2 tt = lut_s[ks*4 + tg];
        unsigned a0 = in_s[tt.x + base];
        unsigned a1 = in_s[tt.x + base + 16];
        unsigned a2 = in_s[tt.y + base];
        unsigned a3 = in_s[tt.y + base + 16];
        u64 bb = w2_s[ks*4 + tg + (size_t)gid*P64];
        mma_tf32(acc, a0, a1, a2, a3, (unsigned)bb, (unsigned)(bb >> 32));
    }

    const int oy = oy0 + (mt >> 3);
    const int x0 = (mt & 7)*16;
    #pragma unroll
    for (int half = 0; half < 2; half++) {
        int x = x0 + gid + half*8;
        float* op = out + (size_t)n*8*16384 + (size_t)oy*128 + x;
        #pragma unroll
        for (int e = 0; e < 2; e++) {
            int co = 2*tg + e;
            float v = fmaxf(acc[half*2 + e] + bias[co], 0.f);
            op[(size_t)co*16384] = v;
        }
    }
}

// =====================================================================
// Fused tail: conv4 -> conv5 -> conv6 -> conv7 -> blur precompute.
// =====================================================================
__global__ __launch_bounds__(256) void tail_k(
    const float* __restrict__ t3g,
    const float* __restrict__ c4w, const float* __restrict__ c4b,
    const float* __restrict__ c5w, const float* __restrict__ c5b,
    const float* __restrict__ c6w, const float* __restrict__ c6b,
    const float* __restrict__ c7w, const float* __restrict__ c7b,
    const float* __restrict__ r1w, const float* __restrict__ pw,
    float* __restrict__ contrib, float* __restrict__ pwblur)
{
    extern __shared__ float sm[];
    float* t3s = sm;
    float* w4  = t3s + 4096;
    float* b4  = w4 + 720;
    float* t4s = b4 + 20;
    float* w5  = t4s + 5120;
    float* b5  = w5 + 16000;
    float* t5s = b5 + 32;
    float* w6  = t5s + 1920;
    float* b6  = w6 + 2160;
    float* t6s = b6 + 8;
    float* w7  = t6s + 128;
    float* b7  = w7 + 8;
    float* blur_s = b7 + 1;

    const int n = blockIdx.x;
    const int tid = threadIdx.x;

    for (int i = tid; i < 4096; i += 256) t3s[i] = t3g[(size_t)n*4096 + i];
    for (int i = tid; i < 720; i += 256) { int co = i % 20, r = i / 20; w4[i] = c4w[co*36 + r]; }
    if (tid < 20) b4[tid] = c4b[tid];
    for (int i = tid; i < 16000; i += 256) {
        int co = i & 31, r = i >> 5;
        w5[i] = (co < 30) ? c5w[co*500 + r] : 0.f;
    }
    if (tid < 32) b5[tid] = (tid < 30) ? c5b[tid] : 0.f;
    for (int i = tid; i < 2160; i += 256) { int co = i & 7, r = i >> 3; w6[i] = c6w[co*270 + r]; }
    if (tid < 8) b6[tid] = c6b[tid];
    if (tid < 8) w7[tid] = c7w[tid];
    if (tid == 0) b7[0] = c7b[0];
    __syncthreads();

    {
        int oy = tid >> 4, ox = tid & 15;
        u64 acc[10];
        #pragma unroll
        for (int j = 0; j < 10; j++) acc[j] = pack2(b4[2*j], b4[2*j+1]);
        #pragma unroll 1
        for (int ci = 0; ci < 4; ci++) {
            #pragma unroll
            for (int ky = 0; ky < 3; ky++) {
                int iy = 2*oy - 1 + ky;
                if ((unsigned)iy >= 32u) continue;
                #pragma unroll
                for (int kx = 0; kx < 3; kx++) {
                    int ix = 2*ox - 1 + kx;
                    if ((unsigned)ix >= 32u) continue;
                    u64 v = bcast2(t3s[ci*1024 + iy*32 + ix]);
                    const float* wr = &w4[((ci*3+ky)*3+kx)*20];
                    #pragma unroll
                    for (int j = 0; j < 10; j += 2) {
                        ulonglong2 wq = *reinterpret_cast<const ulonglong2*>(wr + 2*j);
                        fma2(acc[j],   v, wq.x);
                        fma2(acc[j+1], v, wq.y);
                    }
                }
            }
        }
        #pragma unroll
        for (int j = 0; j < 10; j++) {
            float2 a = unpack2(acc[j]);
            t4s[(2*j)  *256 + tid] = fmaxf(a.x, 0.f);
            t4s[(2*j+1)*256 + tid] = fmaxf(a.y, 0.f);
        }
    }
    __syncthreads();

    {
        int px = tid & 63, grp = tid >> 6;
        int oy = px >> 3, ox = px & 7;
        u64 acc[4];
        #pragma unroll
        for (int j = 0; j < 4; j++) acc[j] = pack2(b5[grp*8+2*j], b5[grp*8+2*j+1]);
        #pragma unroll 1
        for (int ci = 0; ci < 20; ci++) {
            #pragma unroll
            for (int ky = 0; ky < 5; ky++) {
                int iy = 2*oy - 2 + ky;
                if ((unsigned)iy >= 16u) continue;
                #pragma unroll
                for (int kx = 0; kx < 5; kx++) {
                    int ix = 2*ox - 2 + kx;
                    if ((unsigned)ix >= 16u) continue;
                    u64 v = bcast2(t4s[ci*256 + iy*16 + ix]);
                    const float* wr = &w5[((ci*5+ky)*5+kx)*32 + grp*8];
                    #pragma unroll
                    for (int j = 0; j < 4; j += 2) {
                        ulonglong2 wq = *reinterpret_cast<const ulonglong2*>(wr + 2*j);
                        fma2(acc[j],   v, wq.x);
                        fma2(acc[j+1], v, wq.y);
                    }
                }
            }
        }
        #pragma unroll
        for (int j = 0; j < 4; j++) {
            float2 a = unpack2(acc[j]);
            int c0 = grp*8 + 2*j;
            if (c0   < 30) t5s[(c0)  *64 + px] = fmaxf(a.x, 0.f);
            if (c0+1 < 30) t5s[(c0+1)*64 + px] = fmaxf(a.y, 0.f);
        }
    }
    __syncthreads();

    if (tid < 16) {
        int oy = tid >> 2, ox = tid & 3;
        u64 acc[4];
        #pragma unroll
        for (int j = 0; j < 4; j++) acc[j] = pack2(b6[2*j], b6[2*j+1]);
        #pragma unroll 1
        for (int ci = 0; ci < 30; ci++) {
            #pragma unroll
            for (int ky = 0; ky < 3; ky++) {
                int iy = 2*oy - 1 + ky;
                if ((unsigned)iy >= 8u) continue;
                #pragma unroll
                for (int kx = 0; kx < 3; kx++) {
                    int ix = 2*ox - 1 + kx;
                    if ((unsigned)ix >= 8u) continue;
                    u64 v = bcast2(t5s[ci*64 + iy*8 + ix]);
                    const float* wr = &w6[((ci*3+ky)*3+kx)*8];
                    #pragma unroll
                    for (int j = 0; j < 4; j += 2) {
                        ulonglong2 wq = *reinterpret_cast<const ulonglong2*>(wr + 2*j);
                        fma2(acc[j],   v, wq.x);
                        fma2(acc[j+1], v, wq.y);
                    }
                }
            }
        }
        #pragma unroll
        for (int j = 0; j < 4; j++) {
            float2 a = unpack2(acc[j]);
            t6s[(2*j)  *16 + tid] = fmaxf(a.x, 0.f);
            t6s[(2*j+1)*16 + tid] = fmaxf(a.y, 0.f);
        }
    }
    __syncthreads();

    if (tid < 16) {
        float acc = b7[0];
        #pragma unroll
        for (int ci = 0; ci < 8; ci++)
            acc = fmaf(t6s[ci*16 + tid], w7[ci], acc);
        blur_s[tid] = fmaxf(acc, 0.f);
    }
    __syncthreads();

    if (tid < 64) {
        int co = tid;
        float s[9];
        #pragma unroll
        for (int q = 0; q < 9; q++) s[q] = 0.f;
        for (int ci = 0; ci < 16; ci++) {
            float bv = blur_s[ci];
            const float* tw = r1w + ((size_t)co*48 + ci)*9;
            float t[9];
            #pragma unroll
            for (int q = 0; q < 9; q++) t[q] = tw[q];
            float cs[3][3];
            #pragma unroll
            for (int ky = 0; ky < 3; ky++) {
                cs[ky][0] = t[ky*3+1] + t[ky*3+2];
                cs[ky][1] = t[ky*3+0] + t[ky*3+1] + t[ky*3+2];
                cs[ky][2] = t[ky*3+0] + t[ky*3+1];
            }
            #pragma unroll
            for (int vx = 0; vx < 3; vx++) {
                float r0 = cs[1][vx] + cs[2][vx];
                float r1v = cs[0][vx] + cs[1][vx] + cs[2][vx];
                float r2 = cs[0][vx] + cs[1][vx];
                s[0*3+vx] = fmaf(bv, r0,  s[0*3+vx]);
                s[1*3+vx] = fmaf(bv, r1v, s[1*3+vx]);
                s[2*3+vx] = fmaf(bv, r2,  s[2*3+vx]);
            }
        }
        #pragma unroll
        for (int q = 0; q < 9; q++) contrib[((size_t)n*9 + q)*64 + co] = s[q];
    } else if (tid >= 64 && tid < 84) {
        int co = tid - 64;
        float q = 0.f;
        for (int ci = 0; ci < 16; ci++)
            q = fmaf(blur_s[ci], pw[co*48 + ci], q);
        pwblur[n*20 + co] = q;
    }
}

// ---------------- BN finalize --------------------------------------------
template<int C>
__global__ void bn_fin2_k(const float* __restrict__ part, const float* __restrict__ g,
                          const float* __restrict__ be, float* __restrict__ scale,
                          float* __restrict__ shift)
{
    int c = blockIdx.x;
    __shared__ float rs[256], rs2[256];
    float s = 0.f, s2 = 0.f;
    for (int i = threadIdx.x; i < 1024; i += 256) {
        s  += part[(size_t)c*1024 + i];
        s2 += part[(size_t)C*1024 + (size_t)c*1024 + i];
    }
    rs[threadIdx.x] = s; rs2[threadIdx.x] = s2;
    __syncthreads();
    for (int o = 128; o > 0; o >>= 1) {
        if (threadIdx.x < o) {
            rs[threadIdx.x]  += rs[threadIdx.x + o];
            rs2[threadIdx.x] += rs2[threadIdx.x + o];
        }
        __syncthreads();
    }
    if (threadIdx.x == 0) {
        const float cnt = (float)NB * 4096.f;
        float mu  = rs[0] / cnt;
        float var = rs2[0] / cnt - mu*mu;
        float sc  = g[c] * rsqrtf(var + 1e-5f);
        scale[c] = sc;
        shift[c] = be[c] - mu*sc;
    }
}

// ---------------- bn2 apply + pointwise(ds) + pwblur residual --------------
__global__ __launch_bounds__(128) void bn2pw_k(
    float* __restrict__ r2, const float* __restrict__ pwblur,
    const float* __restrict__ ds, const float* __restrict__ pw,
    const float* __restrict__ pb, const float* __restrict__ scale,
    const float* __restrict__ shift)
{
    __shared__ float sw[32*20];
    __shared__ float sb[20], ssc[20], ssh[20];
    for (int i = threadIdx.x; i < 32*20; i += blockDim.x) {
        int co = i % 20, ci = i / 20;
        sw[i] = pw[co*48 + 16 + ci];
    }
    if (threadIdx.x < 20) {
        sb[threadIdx.x]  = pb[threadIdx.x];
        ssc[threadIdx.x] = scale[threadIdx.x];
        ssh[threadIdx.x] = shift[threadIdx.x];
    }
    __syncthreads();

    int idx = blockIdx.x*blockDim.x + threadIdx.x;
    if (idx >= NB*4096) return;
    int p = idx & 4095; int n = idx >> 12;

    u64 acc[10];
    const float* pbl = &pwblur[n*20];
    #pragma unroll
    for (int j = 0; j < 10; j++)
        acc[j] = pack2(sb[2*j] + pbl[2*j], sb[2*j+1] + pbl[2*j+1]);

    const float* dsp = ds + (size_t)n*32*4096 + p;
    #pragma unroll 1
    for (int ci = 0; ci < 32; ci++) {
        u64 v = bcast2(__ldg(&dsp[(size_t)ci*4096]));
        const float* wpp = &sw[ci*20];
        #pragma unroll
        for (int j = 0; j < 10; j += 2) {
            ulonglong2 wq = *reinterpret_cast<const ulonglong2*>(wpp + 2*j);
            fma2(acc[j],   v, wq.x);
            fma2(acc[j+1], v, wq.y);
        }
    }
    float* rp = r2 + (size_t)n*20*4096 + p;
    #pragma unroll
    for (int j = 0; j < 10; j++) {
        float2 a = unpack2(acc[j]);
        int c = 2*j;
        rp[(size_t)c    *4096] = fmaf(rp[(size_t)c    *4096], ssc[c],   ssh[c])   + a.x;
        rp[(size_t)(c+1)*4096] = fmaf(rp[(size_t)(c+1)*4096], ssc[c+1], ssh[c+1]) + a.y;
    }
}

// ---------------- final: u2 1x1 + relu + pixel_shuffle(4) + sigmoid --------
__global__ __launch_bounds__(128) void final_k(
    const float* __restrict__ u1, const float* __restrict__ w,
    const float* __restrict__ b, float* __restrict__ out)
{
    __shared__ float sw[30*16];
    __shared__ float sb[16];
    for (int i = threadIdx.x; i < 30*16; i += blockDim.x) {
        int co = i % 16, ci = i / 16;
        sw[i] = w[co*30 + ci];
    }
    if (threadIdx.x < 16) sb[threadIdx.x] = b[threadIdx.x];
    __syncthreads();

    int idx = blockIdx.x*blockDim.x + threadIdx.x;
    if (idx >= NB*4096) return;
    int wq = idx & 63; int h = (idx >> 6) & 63; int n = idx >> 12;

    u64 acc[8];
    #pragma unroll
    for (int j = 0; j < 8; j++) acc[j] = pack2(sb[2*j], sb[2*j+1]);

    const float* up = u1 + (size_t)n*30*4096 + h*64 + wq;
    #pragma unroll 1
    for (int ci = 0; ci < 30; ci++) {
        u64 v = bcast2(__ldg(&up[(size_t)ci*4096]));
        const float* wpp = &sw[ci*16];
        #pragma unroll
        for (int j = 0; j < 8; j += 2) {
            ulonglong2 wqv = *reinterpret_cast<const ulonglong2*>(wpp + 2*j);
            fma2(acc[j],   v, wqv.x);
            fma2(acc[j+1], v, wqv.y);
        }
    }
    float* op = out + (size_t)n*65536;
    #pragma unroll
    for (int j = 0; j < 8; j++) {
        float2 a = unpack2(acc[j]);
        #pragma unroll
        for (int h2 = 0; h2 < 2; h2++) {
            int c = 2*j + h2;
            float v = fmaxf(h2 ? a.y : a.x, 0.f);
            v = 1.f / (1.f + expf(-v));
            op[(h*4 + (c >> 2))*256 + wq*4 + (c & 3)] = v;
        }
    }
}

// ---------------------------------------------------------------------------
extern "C" void kernel_launch(void* const* d_in, const int* in_sizes, int n_in,
                              void* d_out, int out_size)
{
    const float* x1  = (const float*)d_in[0];
    const float* c1w = (const float*)d_in[1];  const float* c1b = (const float*)d_in[2];
    const float* c2w = (const float*)d_in[3];  const float* c2b = (const float*)d_in[4];
    const float* c3w = (const float*)d_in[5];  const float* c3b = (const float*)d_in[6];
    const float* c4w = (const float*)d_in[7];  const float* c4b = (const float*)d_in[8];
    const float* c5w = (const float*)d_in[9];  const float* c5b = (const float*)d_in[10];
    const float* c6w = (const float*)d_in[11]; const float* c6b = (const float*)d_in[12];
    const float* c7w = (const float*)d_in[13]; const float* c7b = (const float*)d_in[14];
    const float* r1w = (const float*)d_in[15]; const float* r1b = (const float*)d_in[16];
    const float* g1  = (const float*)d_in[17]; const float* be1 = (const float*)d_in[18];
    const float* r2w = (const float*)d_in[19]; const float* r2b = (const float*)d_in[20];
    const float* g2  = (const float*)d_in[21]; const float* be2 = (const float*)d_in[22];
    const float* pw  = (const float*)d_in[23]; const float* pb  = (const float*)d_in[24];
    const float* u1w = (const float*)d_in[25]; const float* u1b = (const float*)d_in[26];
    const float* u2w = (const float*)d_in[27]; const float* u2b = (const float*)d_in[28];

    float *t1,*ds,*t3,*r1,*r2,*u1,*part,*scale,*shift,*contrib,*pwblur;
    cudaGetSymbolAddress((void**)&t1,     g_t1);
    cudaGetSymbolAddress((void**)&ds,     g_ds);
    cudaGetSymbolAddress((void**)&t3,     g_t3);
    cudaGetSymbolAddress((void**)&r1,     g_r1);
    cudaGetSymbolAddress((void**)&r2,     g_r2);
    cudaGetSymbolAddress((void**)&u1,     g_u1);
    cudaGetSymbolAddress((void**)&part,   g_part);
    cudaGetSymbolAddress((void**)&scale,  g_scale);
    cudaGetSymbolAddress((void**)&shift,  g_shift);
    cudaGetSymbolAddress((void**)&contrib,g_contrib);
    cudaGetSymbolAddress((void**)&pwblur, g_pwblur);

    u64 *wp_r1, *wp_r2, *wp_u1, *wp_c2, *wp_c1, *wp_c3;
    cudaGetSymbolAddress((void**)&wp_r1, g_wp_r1);
    cudaGetSymbolAddress((void**)&wp_r2, g_wp_r2);
    cudaGetSymbolAddress((void**)&wp_u1, g_wp_u1);
    cudaGetSymbolAddress((void**)&wp_c2, g_wp_c2);
    cudaGetSymbolAddress((void**)&wp_c1, g_wp_c1);
    cudaGetSymbolAddress((void**)&wp_c3, g_wp_c3);

    auto smemTC = [](int cinc, int coutp, int kp, int kcp) {
        size_t in_s = (size_t)((cinc*10*68 + 3) & ~3);
        return in_s*4 + (size_t)coutp*pad64(kp/2)*8
             + (size_t)(kcp/8)*4*8 + (size_t)32*coutp*2*4;
    };
    size_t sm_r1 = smemTC(16, 64, 2*ceil8i(16*9), ceil8i(16*9));
    size_t sm_r2 = smemTC(16, 24, 4*ceil8i(16*9), ceil8i(16*9));
    size_t sm_u1 = smemTC(20, 32, 1*ceil8i(20*9), ceil8i(20*9));
    size_t sm_c2 = (size_t)(8*11*132)*4 + (size_t)32*100*8 + 100*8;
    size_t sm_c1 = (size_t)1292*4 + (size_t)8*20*8 + 8*8;
    size_t sm_c3 = (size_t)(((8*17*66 + 3) & ~3))*4 + (size_t)8*148*8 + 36*8;
    size_t sm_tail = (size_t)30240*4;

    cudaFuncSetAttribute((const void*)tc_conv3_k<32,16,48,16,64,64,false,false,true,true>,
                         cudaFuncAttributeMaxDynamicSharedMemorySize, (int)sm_r1);
    cudaFuncSetAttribute((const void*)tc_conv3_k<64,16,64,0,20,24,false,true,false,true>,
                         cudaFuncAttributeMaxDynamicSharedMemorySize, (int)sm_r2);
    cudaFuncSetAttribute((const void*)tc_conv3_k<20,20,20,0,30,32,true,false,false,false>,
                         cudaFuncAttributeMaxDynamicSharedMemorySize, (int)sm_u1);
    cudaFuncSetAttribute((const void*)tc_conv2_k,
                         cudaFuncAttributeMaxDynamicSharedMemorySize, (int)sm_c2);
    cudaFuncSetAttribute((const void*)tc_conv3s2_k,
                         cudaFuncAttributeMaxDynamicSharedMemorySize, (int)sm_c3);
    cudaFuncSetAttribute((const void*)tail_k,
                         cudaFuncAttributeMaxDynamicSharedMemorySize, (int)sm_tail);

    // ---------------- merged weight pre-pack -------------
    {
        int total = 64*148 + 24*292 + 2*32*100 + 8*20 + 8*148;
        packall_k<<<(total+127)/128,128>>>(r1w, r2w, u1w, c2w, c1w, c3w,
                                           wp_r1, wp_r2, wp_u1, wp_c2, wp_c1, wp_c3);
    }

    // ---------------- encoder ----------------
    tc_conv1_k<<<dim3(64,NB),512, sm_c1>>>(x1, wp_c1, c1b, t1);
    tc_conv2_k<<<dim3(16,NB),512, sm_c2>>>(t1, wp_c2, c2b, ds);
    tc_conv3s2_k<<<dim3(4,NB),512, sm_c3>>>(ds, wp_c3, c3b, t3);
    tail_k<<<NB,256, sm_tail>>>(t3, c4w, c4b, c5w, c5b, c6w, c6b, c7w, c7b,
                                r1w, pw, contrib, pwblur);

    // ---------------- residual block with training-mode BN ----------------
    tc_conv3_k<32,16,48,16,64,64,false,false,true,true>
        <<<dim3(8,NB),1024, sm_r1>>>(ds, wp_r1, r1b, nullptr, nullptr, contrib, r1, part);
    bn_fin2_k<64><<<64,256>>>(part, g1, be1, scale, shift);

    tc_conv3_k<64,16,64,0,20,24,false,true,false,true>
        <<<dim3(8,NB),1024, sm_r2>>>(r1, wp_r2, r2b, scale, shift, nullptr, r2, part);
    bn_fin2_k<20><<<20,256>>>(part, g2, be2, scale, shift);
    bn2pw_k<<<(NB*4096+127)/128,128>>>(r2, pwblur, ds, pw, pb, scale, shift);

    // ---------------- upsample head ----------------
    tc_conv3_k<20,20,20,0,30,32,true,false,false,false>
        <<<dim3(8,NB),1024, sm_u1>>>(r2, wp_u1, u1b, nullptr, nullptr, nullptr, u1, nullptr);
    final_k<<<(NB*4096+127)/128,128>>>(u1, u2w, u2b, (float*)d_out);
}

// round 17
// speedup vs baseline: 1.1749x; 1.1749x over previous
#include <cuda_runtime.h>
#include <cuda_bf16.h>
#include <math.h>

#define NB 128

// ---------------- scratch ----------------
__device__ float g_t1[(size_t)NB*8*128*128];
__device__ float g_ds[(size_t)NB*32*64*64];
__device__ float g_t3[(size_t)NB*4*32*32];
__device__ float g_r1[(size_t)NB*64*64*64];
__device__ float g_r2[(size_t)NB*20*64*64];
__device__ float g_u1[(size_t)NB*30*64*64];
__device__ float g_part[2*64*1024];
__device__ float g_scale[64];
__device__ float g_shift[64];
__device__ float g_contrib[NB*9*64];
__device__ float g_pwblur[NB*20];

typedef unsigned long long u64;
__device__ __align__(16) u64 g_wp_r1[64*148];
__device__ __align__(16) u64 g_wp_r2[24*292];
__device__ __align__(16) u64 g_wp_u1[32*100];
__device__ __align__(16) u64 g_wp_c2[32*100];
__device__ __align__(16) u64 g_wp_c1[8*20];
__device__ __align__(16) u64 g_wp_c3[8*148];

// ---------------- helpers ----------------
static __device__ __forceinline__ u64 pack2(float x, float y) {
    u64 r; asm("mov.b64 %0, {%1, %2};" : "=l"(r) : "f"(x), "f"(y)); return r;
}
static __device__ __forceinline__ u64 bcast2(float x) { return pack2(x, x); }
static __device__ __forceinline__ void fma2(u64& d, u64 a, u64 b) {
    asm("fma.rn.f32x2 %0, %1, %2, %0;" : "+l"(d) : "l"(a), "l"(b));
}
static __device__ __forceinline__ float2 unpack2(u64 v) {
    float2 r; asm("mov.b64 {%0, %1}, %2;" : "=f"(r.x), "=f"(r.y) : "l"(v)); return r;
}
static __device__ __forceinline__ unsigned to_tf32(float v) {
    unsigned u; asm("cvt.rna.tf32.f32 %0, %1;" : "=r"(u) : "f"(v)); return u;
}
static __device__ __forceinline__ u64 packtf2(float x, float y) {
    return (u64)to_tf32(x) | ((u64)to_tf32(y) << 32);
}
static __device__ __forceinline__ void mma_tf32(
    float* acc, unsigned a0, unsigned a1, unsigned a2, unsigned a3,
    unsigned b0, unsigned b1)
{
    asm volatile(
      "mma.sync.aligned.m16n8k8.row.col.f32.tf32.tf32.f32 "
      "{%0,%1,%2,%3}, {%4,%5,%6,%7}, {%8,%9}, {%0,%1,%2,%3};"
      : "+f"(acc[0]), "+f"(acc[1]), "+f"(acc[2]), "+f"(acc[3])
      : "r"(a0), "r"(a1), "r"(a2), "r"(a3), "r"(b0), "r"(b1));
}

__host__ __device__ constexpr int ceil8i(int x) { return (x + 7) & ~7; }
__host__ __device__ constexpr int pad64(int x) { return x + ((4 - (x & 15)) + 16) % 16; }

// =====================================================================
// Merged weight pre-pack.
// =====================================================================
template<int CIN,int CINC,int WCIN,int CIOFF,int COUT,int COUTP>
static __device__ __forceinline__ u64 pack3_elem(const float* __restrict__ w, int idx)
{
    constexpr int KC  = CINC*9;
    constexpr int KCP = ceil8i(KC);
    constexpr int KP  = (CIN/CINC)*KCP;
    constexpr int P64 = pad64(KP/2);
    int co = idx / P64; int j = idx - co*P64;
    u64 val = 0;
    if (j < (KP/8)*4) {
        int kgrp = j >> 2, tg = j & 3;
        int k0 = kgrp*8 + tg, k1 = k0 + 4;
        int chunk = k0 / KCP;
        int kin0 = k0 - chunk*KCP, kin1 = k1 - chunk*KCP;
        float v0 = 0.f, v1 = 0.f;
        if (co < COUT && kin0 < KC)
            v0 = w[((size_t)co*WCIN + CIOFF + chunk*CINC + kin0/9)*9 + kin0%9];
        if (co < COUT && kin1 < KC)
            v1 = w[((size_t)co*WCIN + CIOFF + chunk*CINC + kin1/9)*9 + kin1%9];
        val = packtf2(v0, v1);
    }
    return val;
}

__global__ void packall_k(const float* __restrict__ r1w, const float* __restrict__ r2w,
                          const float* __restrict__ u1w, const float* __restrict__ c2w,
                          const float* __restrict__ c1w, const float* __restrict__ c3w,
                          u64* __restrict__ wr1, u64* __restrict__ wr2,
                          u64* __restrict__ wu1, u64* __restrict__ wc2,
                          u64* __restrict__ wc1, u64* __restrict__ wc3)
{
    int idx = blockIdx.x*blockDim.x + threadIdx.x;
    if (idx < 64*148) {
        wr1[idx] = pack3_elem<32,16,48,16,64,64>(r1w, idx);
    } else if (idx < 64*148 + 24*292) {
        int i = idx - 64*148;
        wr2[i] = pack3_elem<64,16,64,0,20,24>(r2w, i);
    } else if (idx < 64*148 + 24*292 + 32*100) {
        int i = idx - (64*148 + 24*292);
        wu1[i] = pack3_elem<20,20,20,0,30,32>(u1w, i);
    } else if (idx < 64*148 + 24*292 + 2*32*100) {
        int i = idx - (64*148 + 24*292 + 32*100);
        int co = i / 100; int j = i - co*100;
        int kgrp = j >> 2, tg = j & 3;
        int k0 = kgrp*8 + tg;
        wc2[i] = packtf2(c2w[(size_t)co*200 + k0], c2w[(size_t)co*200 + k0 + 4]);
    } else if (idx < 64*148 + 24*292 + 2*32*100 + 8*20) {
        int i = idx - (64*148 + 24*292 + 2*32*100);
        wc1[i] = pack3_elem<1,1,1,0,8,8>(c1w, i);
    } else if (idx < 64*148 + 24*292 + 2*32*100 + 8*20 + 8*148) {
        int i = idx - (64*148 + 24*292 + 2*32*100 + 8*20);
        wc3[i] = pack3_elem<32,8,32,0,4,8>(c3w, i);
    }
}

// =====================================================================
// Tensor-core 3x3 s1 p1 conv, 8 output rows per block, 1024 threads.
// Staging: flat index over 4-column groups (addressing amortized 4x).
// =====================================================================
template<int CIN,int CINC,int WCIN,int CIOFF,int COUT,int COUTP,bool RELU,bool BNIN,bool CONTRIB,bool STATS>
__global__ __launch_bounds__(1024) void tc_conv3_k(
    const float* __restrict__ in, const u64* __restrict__ wp,
    const float* __restrict__ bias, const float* __restrict__ bnsc,
    const float* __restrict__ bnsh, const float* __restrict__ contrib,
    float* __restrict__ out, float* __restrict__ bnpart)
{
    constexpr int CHUNKS = CIN / CINC;
    static_assert(CIN % CINC == 0 && COUTP % 8 == 0, "");
    constexpr int KC   = CINC*9;
    constexpr int KCP  = ceil8i(KC);
    constexpr int KP   = CHUNKS*KCP;
    constexpr int P64  = pad64(KP/2);
    constexpr int IN_S = (CINC*10*68 + 3) & ~3;
    constexpr int NT   = COUTP/8;
    constexpr int NKS  = KCP/8;
    constexpr int G4   = 17;                 // 4-col groups per row (covers 66)
    extern __shared__ unsigned smu[];
    unsigned* in_s = smu;
    u64*  w2_s = (u64*)(smu + IN_S);
    int2* lut_s = (int2*)(w2_s + (size_t)COUTP*P64);
    float* st_s = (float*)(lut_s + NKS*4);

    const int n   = blockIdx.y;
    const int oy0 = blockIdx.x * 8;
    const int tid = threadIdx.x;
    const int lane = tid & 31;
    const int mt  = tid >> 5;
    const int tg  = lane & 3;
    const int gid = lane >> 2;

    {
        ulonglong2* d = (ulonglong2*)w2_s;
        const ulonglong2* s = (const ulonglong2*)wp;
        for (int i = tid; i < COUTP*P64/2; i += 1024) d[i] = s[i];
    }
    for (int j = tid; j < NKS*4; j += 1024) {
        int ks = j >> 2, tg_ = j & 3;
        int k0 = ks*8 + tg_, k1 = k0 + 4;
        int t0 = 0, t1 = 0;
        if (k0 < KC) { int c = k0/9, tp = k0%9; t0 = (c*10 + tp/3)*68 + tp%3; }
        if (k1 < KC) { int c = k1/9, tp = k1%9; t1 = (c*10 + tp/3)*68 + tp%3; }
        lut_s[j] = make_int2(t0, t1);
    }

    float acc[NT][4];
    #pragma unroll
    for (int nt = 0; nt < NT; nt++)
        #pragma unroll
        for (int e = 0; e < 4; e++) acc[nt][e] = 0.f;

    const int base = (mt >> 2)*68 + (mt & 3)*16 + gid;

    for (int chunk = 0; chunk < CHUNKS; chunk++) {
        __syncthreads();
        const int ci0 = chunk*CINC;
        for (int g = tid; g < CINC*10*G4; g += 1024) {
            int ci = g / (10*G4); int rem = g - ci*(10*G4);
            int ry = rem / G4; int c4 = (rem - ry*G4)*4;
            int iy = oy0 - 1 + ry;
            unsigned* dst = in_s + (ci*10 + ry)*68 + c4;
            bool rowok = ((unsigned)iy < 64u);
            const float* src = in + ((size_t)n*CIN + ci0 + ci)*4096 + iy*64;
            float sc = 0.f, sh = 0.f;
            if (BNIN && rowok) { sc = bnsc[ci0+ci]; sh = bnsh[ci0+ci]; }
            #pragma unroll
            for (int j = 0; j < 4; j++) {
                int cx = c4 + j;
                if (cx < 66) {
                    int ix = cx - 1;
                    float val = 0.f;
                    if (rowok && (unsigned)ix < 64u) {
                        val = src[ix];
                        if (BNIN) val = fmaxf(fmaf(val, sc, sh), 0.f);
                    }
                    dst[j] = to_tf32(val);
                }
            }
        }
        __syncthreads();

        const u64* wc = w2_s + chunk*NKS*4 + tg + (size_t)gid*P64;
        #pragma unroll
        for (int ks = 0; ks < NKS; ks++) {
            int2 tt = lut_s[ks*4 + tg];
            unsigned a0 = in_s[tt.x + base];
            unsigned a1 = in_s[tt.x + base + 8];
            unsigned a2 = in_s[tt.y + base];
            unsigned a3 = in_s[tt.y + base + 8];
            #pragma unroll
            for (int nt = 0; nt < NT; nt++) {
                u64 bb = wc[ks*4 + (size_t)(nt*8)*P64];
                mma_tf32(acc[nt], a0, a1, a2, a3, (unsigned)bb, (unsigned)(bb >> 32));
            }
        }
    }

    const int oy = oy0 + (mt >> 2);
    const int x0 = (mt & 3)*16;
    const int vy = (oy == 0) ? 0 : ((oy == 63) ? 2 : 1);
    float sacc[NT][2], s2acc[NT][2];
    if (STATS) {
        #pragma unroll
        for (int nt = 0; nt < NT; nt++) { sacc[nt][0]=sacc[nt][1]=0.f; s2acc[nt][0]=s2acc[nt][1]=0.f; }
    }
    #pragma unroll
    for (int half = 0; half < 2; half++) {
        int x = x0 + gid + half*8;
        int vx = (x == 0) ? 0 : ((x == 63) ? 2 : 1);
        const float* cp = CONTRIB ? &contrib[((size_t)n*9 + vy*3 + vx)*64] : nullptr;
        float* op = out + (size_t)n*COUT*4096 + (size_t)oy*64 + x;
        #pragma unroll
        for (int nt = 0; nt < NT; nt++) {
            #pragma unroll
            for (int e = 0; e < 2; e++) {
                int co = nt*8 + 2*tg + e;
                float bv = (co < COUT) ? bias[co] : 0.f;
                float v = acc[nt][half*2 + e] + bv;
                if (CONTRIB) v += (co < COUT) ? cp[co] : 0.f;
                if (RELU) v = fmaxf(v, 0.f);
                if (co < COUT) op[(size_t)co*4096] = v;
                if (STATS) { sacc[nt][e] += v; s2acc[nt][e] += v*v; }
            }
        }
    }
    if (STATS) {
        #pragma unroll
        for (int nt = 0; nt < NT; nt++) {
            #pragma unroll
            for (int e = 0; e < 2; e++) {
                float s = sacc[nt][e], s2 = s2acc[nt][e];
                s  += __shfl_xor_sync(0xffffffffu, s, 4);
                s2 += __shfl_xor_sync(0xffffffffu, s2, 4);
                s  += __shfl_xor_sync(0xffffffffu, s, 8);
                s2 += __shfl_xor_sync(0xffffffffu, s2, 8);
                s  += __shfl_xor_sync(0xffffffffu, s, 16);
                s2 += __shfl_xor_sync(0xffffffffu, s2, 16);
                if (gid == 0) {
                    int co = nt*8 + 2*tg + e;
                    st_s[(mt*COUTP + co)*2 + 0] = s;
                    st_s[(mt*COUTP + co)*2 + 1] = s2;
                }
            }
        }
        __syncthreads();
        if (tid < COUT) {
            float S = 0.f, S2 = 0.f;
            #pragma unroll
            for (int wq = 0; wq < 32; wq++) {
                S  += st_s[(wq*COUTP + tid)*2 + 0];
                S2 += st_s[(wq*COUTP + tid)*2 + 1];
            }
            int blk = blockIdx.y*gridDim.x + blockIdx.x;
            bnpart[(size_t)tid*1024 + blk] = S;
            bnpart[(size_t)COUT*1024 + (size_t)tid*1024 + blk] = S2;
        }
    }
}

// =====================================================================
// Tensor-core conv2: 8->32, k5, s2, p2, 128->64. 4-col group staging.
// =====================================================================
__global__ __launch_bounds__(512) void tc_conv2_k(
    const float* __restrict__ in, const u64* __restrict__ wp,
    const float* __restrict__ bias, float* __restrict__ out)
{
    constexpr int IN_S = 8*11*132;
    constexpr int G4 = 33;                  // covers 131
    extern __shared__ unsigned smu[];
    unsigned* in_s = smu;
    u64*  w2_s = (u64*)(smu + IN_S);
    int2* lut_s = (int2*)(w2_s + 32*100);

    const int n   = blockIdx.y;
    const int oy0 = blockIdx.x * 4;
    const int tid = threadIdx.x;
    const int lane = tid & 31;
    const int mt  = tid >> 5;
    const int tg  = lane & 3;
    const int gid = lane >> 2;

    {
        ulonglong2* d = (ulonglong2*)w2_s;
        const ulonglong2* s = (const ulonglong2*)wp;
        for (int i = tid; i < 32*100/2; i += 512) d[i] = s[i];
    }
    for (int j = tid; j < 100; j += 512) {
        int ks = j >> 2, tg_ = j & 3;
        int k0 = ks*8 + tg_, k1 = k0 + 4;
        int c0 = k0/25, r0 = k0%25, c1 = k1/25, r1 = k1%25;
        lut_s[j] = make_int2((c0*11 + r0/5)*132 + r0%5,
                             (c1*11 + r1/5)*132 + r1%5);
    }
    for (int g = tid; g < 8*11*G4; g += 512) {
        int ci = g / (11*G4); int rem = g - ci*(11*G4);
        int ry = rem / G4; int c4 = (rem - ry*G4)*4;
        int iy = 2*oy0 - 2 + ry;
        unsigned* dst = in_s + (ci*11 + ry)*132 + c4;
        bool rowok = ((unsigned)iy < 128u);
        const float* src = in + ((size_t)n*8 + ci)*16384 + iy*128;
        #pragma unroll
        for (int j = 0; j < 4; j++) {
            int cx = c4 + j;
            if (cx < 131) {
                int ix = cx - 2;
                float val = (rowok && (unsigned)ix < 128u) ? src[ix] : 0.f;
                dst[j] = to_tf32(val);
            }
        }
    }
    __syncthreads();

    float acc[4][4];
    #pragma unroll
    for (int nt = 0; nt < 4; nt++)
        #pragma unroll
        for (int e = 0; e < 4; e++) acc[nt][e] = 0.f;

    const int base = (mt >> 2)*264 + (mt & 3)*32 + 2*gid;
    const u64* wc = w2_s + tg + (size_t)gid*100;
    #pragma unroll
    for (int ks = 0; ks < 25; ks++) {
        int2 tt = lut_s[ks*4 + tg];
        unsigned a0 = in_s[tt.x + base];
        unsigned a1 = in_s[tt.x + base + 16];
        unsigned a2 = in_s[tt.y + base];
        unsigned a3 = in_s[tt.y + base + 16];
        #pragma unroll
        for (int nt = 0; nt < 4; nt++) {
            u64 bb = wc[ks*4 + (size_t)(nt*8)*100];
            mma_tf32(acc[nt], a0, a1, a2, a3, (unsigned)bb, (unsigned)(bb >> 32));
        }
    }

    const int oy = oy0 + (mt >> 2);
    const int x0 = (mt & 3)*16;
    #pragma unroll
    for (int half = 0; half < 2; half++) {
        int x = x0 + gid + half*8;
        float* op = out + (size_t)n*32*4096 + (size_t)oy*64 + x;
        #pragma unroll
        for (int nt = 0; nt < 4; nt++) {
            #pragma unroll
            for (int e = 0; e < 2; e++) {
                int co = nt*8 + 2*tg + e;
                float v = fmaxf(acc[nt][half*2 + e] + bias[co], 0.f);
                op[(size_t)co*4096] = v;
            }
        }
    }
}

// =====================================================================
// Tensor-core conv3: 32->4, k3, s2, p1, 64->32. 4-col group staging.
// =====================================================================
__global__ __launch_bounds__(512) void tc_conv3s2_k(
    const float* __restrict__ in, const u64* __restrict__ wp,
    const float* __restrict__ bias, float* __restrict__ out)
{
    constexpr int CINC = 8, CHUNKS = 4;
    constexpr int KC = 72, NKS = 9;
    constexpr int P64 = pad64(288/2);    // 148
    constexpr int IN_S = (CINC*17*66 + 3) & ~3;
    constexpr int G4 = 17;               // covers 66
    extern __shared__ unsigned smu[];
    unsigned* in_s = smu;
    u64*  w2_s = (u64*)(smu + IN_S);
    int2* lut_s = (int2*)(w2_s + 8*P64);

    const int n   = blockIdx.y;
    const int oy0 = blockIdx.x * 8;
    const int tid = threadIdx.x;
    const int lane = tid & 31;
    const int mt  = tid >> 5;
    const int tg  = lane & 3;
    const int gid = lane >> 2;

    {
        ulonglong2* d = (ulonglong2*)w2_s;
        const ulonglong2* s = (const ulonglong2*)wp;
        for (int i = tid; i < 8*P64/2; i += 512) d[i] = s[i];
    }
    for (int j = tid; j < NKS*4; j += 512) {
        int ks = j >> 2, tg_ = j & 3;
        int k0 = ks*8 + tg_, k1 = k0 + 4;
        int t0 = 0, t1 = 0;
        if (k0 < KC) { int c = k0/9, tp = k0%9; t0 = (c*17 + tp/3)*66 + tp%3; }
        if (k1 < KC) { int c = k1/9, tp = k1%9; t1 = (c*17 + tp/3)*66 + tp%3; }
        lut_s[j] = make_int2(t0, t1);
    }

    float acc[4] = {0.f, 0.f, 0.f, 0.f};
    const int base = (mt >> 1)*2*66 + ((mt & 1)*16 + gid)*2;

    for (int chunk = 0; chunk < CHUNKS; chunk++) {
        __syncthreads();
        const int ci0 = chunk*CINC;
        for (int g = tid; g < CINC*17*G4; g += 512) {
            int ci = g / (17*G4); int rem = g - ci*(17*G4);
            int ry = rem / G4; int c4 = (rem - ry*G4)*4;
            int iy = 2*oy0 - 1 + ry;
            unsigned* dst = in_s + (ci*17 + ry)*66 + c4;
            bool rowok = ((unsigned)iy < 64u);
            const float* src = in + ((size_t)n*32 + ci0 + ci)*4096 + iy*64;
            #pragma unroll
            for (int j = 0; j < 4; j++) {
                int cx = c4 + j;
                if (cx < 66) {
                    int ix = cx - 1;
                    float val = (rowok && (unsigned)ix < 64u) ? src[ix] : 0.f;
                    dst[j] = to_tf32(val);
                }
            }
        }
        __syncthreads();

        const u64* wc = w2_s + chunk*NKS*4 + tg + (size_t)gid*P64;
        #pragma unroll
        for (int ks = 0; ks < NKS; ks++) {
            int2 tt = lut_s[ks*4 + tg];
            unsigned a0 = in_s[tt.x + base];
            unsigned a1 = in_s[tt.x + base + 16];
            unsigned a2 = in_s[tt.y + base];
            unsigned a3 = in_s[tt.y + base + 16];
            u64 bb = wc[ks*4];
            mma_tf32(acc, a0, a1, a2, a3, (unsigned)bb, (unsigned)(bb >> 32));
        }
    }

    const int oy = oy0 + (mt >> 1);
    const int x0 = (mt & 1)*16;
    #pragma unroll
    for (int half = 0; half < 2; half++) {
        int x = x0 + gid + half*8;
        float* op = out + (size_t)n*4*1024 + (size_t)oy*32 + x;
        #pragma unroll
        for (int e = 0; e < 2; e++) {
            int co = 2*tg + e;
            if (co < 4)
                op[(size_t)co*1024] = acc[half*2 + e] + bias[co];
        }
    }
}

// =====================================================================
// Tensor-core conv1: 1->8, k3, s2, p1, 256->128. 4-col group staging.
// =====================================================================
__global__ __launch_bounds__(512) void tc_conv1_k(
    const float* __restrict__ in, const u64* __restrict__ wp,
    const float* __restrict__ bias, float* __restrict__ out)
{
    constexpr int P64 = 20;
    constexpr int IN_RAW = 5*258;
    constexpr int IN_S = (IN_RAW + 3) & ~3;
    constexpr int G4 = 65;               // covers 258
    extern __shared__ unsigned smu[];
    unsigned* in_s = smu;
    u64*  w2_s = (u64*)(smu + IN_S);
    int2* lut_s = (int2*)(w2_s + 8*20);

    const int n   = blockIdx.y;
    const int oy0 = blockIdx.x * 2;
    const int tid = threadIdx.x;
    const int lane = tid & 31;
    const int mt  = tid >> 5;
    const int tg  = lane & 3;
    const int gid = lane >> 2;

    if (tid < 80) {
        ((ulonglong2*)w2_s)[tid] = ((const ulonglong2*)wp)[tid];
    }
    if (tid < 8) {
        int ks = tid >> 2, tg_ = tid & 3;
        int k0 = ks*8 + tg_, k1 = k0 + 4;
        int t0 = (k0 < 9) ? (k0/3)*258 + k0%3 : 0;
        int t1 = (k1 < 9) ? (k1/3)*258 + k1%3 : 0;
        lut_s[tid] = make_int2(t0, t1);
    }
    for (int g = tid; g < 5*G4; g += 512) {
        int ry = g / G4; int c4 = (g - ry*G4)*4;
        int iy = 2*oy0 - 1 + ry;
        unsigned* dst = in_s + ry*258 + c4;
        bool rowok = ((unsigned)iy < 256u);
        const float* src = in + (size_t)n*65536 + iy*256;
        #pragma unroll
        for (int j = 0; j < 4; j++) {
            int cx = c4 + j;
            if (cx < 258) {
                int ix = cx - 1;
                float val = (rowok && (unsigned)ix < 256u) ? src[ix] : 0.f;
                dst[j] = to_tf32(val);
            }
        }
    }
    __syncthreads();

    float acc[4] = {0.f, 0.f, 0.f, 0.f};
    const int base = (mt >> 3)*516 + ((mt & 7)*16 + gid)*2;
    #pragma unroll
    for (int ks = 0; ks < 2; ks++) {
        int2 tt = lut_s[ks*4 + tg];
        unsigned a0 = in_s[tt.x + base];
        unsigned a1 = in_s[tt.x + base + 16];
        unsigned a2 = in_s[tt.y + base];
        unsigned a3 = in_s[tt.y + base + 16];
        u64 bb = w2_s[ks*4 + tg + (size_t)gid*P64];
        mma_tf32(acc, a0, a1, a2, a3, (unsigned)bb, (unsigned)(bb >> 32));
    }

    const int oy = oy0 + (mt >> 3);
    const int x0 = (mt & 7)*16;
    #pragma unroll
    for (int half = 0; half < 2; half++) {
        int x = x0 + gid + half*8;
        float* op = out + (size_t)n*8*16384 + (size_t)oy*128 + x;
        #pragma unroll
        for (int e = 0; e < 2; e++) {
            int co = 2*tg + e;
            float v = fmaxf(acc[half*2 + e] + bias[co], 0.f);
            op[(size_t)co*16384] = v;
        }
    }
}

// =====================================================================
// Fused tail: conv4 -> conv5 -> conv6 -> conv7 -> blur precompute.
// =====================================================================
__global__ __launch_bounds__(256) void tail_k(
    const float* __restrict__ t3g,
    const float* __restrict__ c4w, const float* __restrict__ c4b,
    const float* __restrict__ c5w, const float* __restrict__ c5b,
    const float* __restrict__ c6w, const float* __restrict__ c6b,
    const float* __restrict__ c7w, const float* __restrict__ c7b,
    const float* __restrict__ r1w, const float* __restrict__ pw,
    float* __restrict__ contrib, float* __restrict__ pwblur)
{
    extern __shared__ float sm[];
    float* t3s = sm;
    float* w4  = t3s + 4096;
    float* b4  = w4 + 720;
    float* t4s = b4 + 20;
    float* w5  = t4s + 5120;
    float* b5  = w5 + 16000;
    float* t5s = b5 + 32;
    float* w6  = t5s + 1920;
    float* b6  = w6 + 2160;
    float* t6s = b6 + 8;
    float* w7  = t6s + 128;
    float* b7  = w7 + 8;
    float* blur_s = b7 + 1;

    const int n = blockIdx.x;
    const int tid = threadIdx.x;

    for (int i = tid; i < 4096; i += 256) t3s[i] = t3g[(size_t)n*4096 + i];
    for (int i = tid; i < 720; i += 256) { int co = i % 20, r = i / 20; w4[i] = c4w[co*36 + r]; }
    if (tid < 20) b4[tid] = c4b[tid];
    for (int i = tid; i < 16000; i += 256) {
        int co = i & 31, r = i >> 5;
        w5[i] = (co < 30) ? c5w[co*500 + r] : 0.f;
    }
    if (tid < 32) b5[tid] = (tid < 30) ? c5b[tid] : 0.f;
    for (int i = tid; i < 2160; i += 256) { int co = i & 7, r = i >> 3; w6[i] = c6w[co*270 + r]; }
    if (tid < 8) b6[tid] = c6b[tid];
    if (tid < 8) w7[tid] = c7w[tid];
    if (tid == 0) b7[0] = c7b[0];
    __syncthreads();

    {
        int oy = tid >> 4, ox = tid & 15;
        u64 acc[10];
        #pragma unroll
        for (int j = 0; j < 10; j++) acc[j] = pack2(b4[2*j], b4[2*j+1]);
        #pragma unroll 1
        for (int ci = 0; ci < 4; ci++) {
            #pragma unroll
            for (int ky = 0; ky < 3; ky++) {
                int iy = 2*oy - 1 + ky;
                if ((unsigned)iy >= 32u) continue;
                #pragma unroll
                for (int kx = 0; kx < 3; kx++) {
                    int ix = 2*ox - 1 + kx;
                    if ((unsigned)ix >= 32u) continue;
                    u64 v = bcast2(t3s[ci*1024 + iy*32 + ix]);
                    const float* wr = &w4[((ci*3+ky)*3+kx)*20];
                    #pragma unroll
                    for (int j = 0; j < 10; j += 2) {
                        ulonglong2 wq = *reinterpret_cast<const ulonglong2*>(wr + 2*j);
                        fma2(acc[j],   v, wq.x);
                        fma2(acc[j+1], v, wq.y);
                    }
                }
            }
        }
        #pragma unroll
        for (int j = 0; j < 10; j++) {
            float2 a = unpack2(acc[j]);
            t4s[(2*j)  *256 + tid] = fmaxf(a.x, 0.f);
            t4s[(2*j+1)*256 + tid] = fmaxf(a.y, 0.f);
        }
    }
    __syncthreads();

    {
        int px = tid & 63, grp = tid >> 6;
        int oy = px >> 3, ox = px & 7;
        u64 acc[4];
        #pragma unroll
        for (int j = 0; j < 4; j++) acc[j] = pack2(b5[grp*8+2*j], b5[grp*8+2*j+1]);
        #pragma unroll 1
        for (int ci = 0; ci < 20; ci++) {
            #pragma unroll
            for (int ky = 0; ky < 5; ky++) {
                int iy = 2*oy - 2 + ky;
                if ((unsigned)iy >= 16u) continue;
                #pragma unroll
                for (int kx = 0; kx < 5; kx++) {
                    int ix = 2*ox - 2 + kx;
                    if ((unsigned)ix >= 16u) continue;
                    u64 v = bcast2(t4s[ci*256 + iy*16 + ix]);
                    const float* wr = &w5[((ci*5+ky)*5+kx)*32 + grp*8];
                    #pragma unroll
                    for (int j = 0; j < 4; j += 2) {
                        ulonglong2 wq = *reinterpret_cast<const ulonglong2*>(wr + 2*j);
                        fma2(acc[j],   v, wq.x);
                        fma2(acc[j+1], v, wq.y);
                    }
                }
            }
        }
        #pragma unroll
        for (int j = 0; j < 4; j++) {
            float2 a = unpack2(acc[j]);
            int c0 = grp*8 + 2*j;
            if (c0   < 30) t5s[(c0)  *64 + px] = fmaxf(a.x, 0.f);
            if (c0+1 < 30) t5s[(c0+1)*64 + px] = fmaxf(a.y, 0.f);
        }
    }
    __syncthreads();

    if (tid < 16) {
        int oy = tid >> 2, ox = tid & 3;
        u64 acc[4];
        #pragma unroll
        for (int j = 0; j < 4; j++) acc[j] = pack2(b6[2*j], b6[2*j+1]);
        #pragma unroll 1
        for (int ci = 0; ci < 30; ci++) {
            #pragma unroll
            for (int ky = 0; ky < 3; ky++) {
                int iy = 2*oy - 1 + ky;
                if ((unsigned)iy >= 8u) continue;
                #pragma unroll
                for (int kx = 0; kx < 3; kx++) {
                    int ix = 2*ox - 1 + kx;
                    if ((unsigned)ix >= 8u) continue;
                    u64 v = bcast2(t5s[ci*64 + iy*8 + ix]);
                    const float* wr = &w6[((ci*3+ky)*3+kx)*8];
                    #pragma unroll
                    for (int j = 0; j < 4; j += 2) {
                        ulonglong2 wq = *reinterpret_cast<const ulonglong2*>(wr + 2*j);
                        fma2(acc[j],   v, wq.x);
                        fma2(acc[j+1], v, wq.y);
                    }
                }
            }
        }
        #pragma unroll
        for (int j = 0; j < 4; j++) {
            float2 a = unpack2(acc[j]);
            t6s[(2*j)  *16 + tid] = fmaxf(a.x, 0.f);
            t6s[(2*j+1)*16 + tid] = fmaxf(a.y, 0.f);
        }
    }
    __syncthreads();

    if (tid < 16) {
        float acc = b7[0];
        #pragma unroll
        for (int ci = 0; ci < 8; ci++)
            acc = fmaf(t6s[ci*16 + tid], w7[ci], acc);
        blur_s[tid] = fmaxf(acc, 0.f);
    }
    __syncthreads();

    if (tid < 64) {
        int co = tid;
        float s[9];
        #pragma unroll
        for (int q = 0; q < 9; q++) s[q] = 0.f;
        for (int ci = 0; ci < 16; ci++) {
            float bv = blur_s[ci];
            const float* tw = r1w + ((size_t)co*48 + ci)*9;
            float t[9];
            #pragma unroll
            for (int q = 0; q < 9; q++) t[q] = tw[q];
            float cs[3][3];
            #pragma unroll
            for (int ky = 0; ky < 3; ky++) {
                cs[ky][0] = t[ky*3+1] + t[ky*3+2];
                cs[ky][1] = t[ky*3+0] + t[ky*3+1] + t[ky*3+2];
                cs[ky][2] = t[ky*3+0] + t[ky*3+1];
            }
            #pragma unroll
            for (int vx = 0; vx < 3; vx++) {
                float r0 = cs[1][vx] + cs[2][vx];
                float r1v = cs[0][vx] + cs[1][vx] + cs[2][vx];
                float r2 = cs[0][vx] + cs[1][vx];
                s[0*3+vx] = fmaf(bv, r0,  s[0*3+vx]);
                s[1*3+vx] = fmaf(bv, r1v, s[1*3+vx]);
                s[2*3+vx] = fmaf(bv, r2,  s[2*3+vx]);
            }
        }
        #pragma unroll
        for (int q = 0; q < 9; q++) contrib[((size_t)n*9 + q)*64 + co] = s[q];
    } else if (tid >= 64 && tid < 84) {
        int co = tid - 64;
        float q = 0.f;
        for (int ci = 0; ci < 16; ci++)
            q = fmaf(blur_s[ci], pw[co*48 + ci], q);
        pwblur[n*20 + co] = q;
    }
}

// ---------------- BN finalize --------------------------------------------
template<int C>
__global__ void bn_fin2_k(const float* __restrict__ part, const float* __restrict__ g,
                          const float* __restrict__ be, float* __restrict__ scale,
                          float* __restrict__ shift)
{
    int c = blockIdx.x;
    __shared__ float rs[256], rs2[256];
    float s = 0.f, s2 = 0.f;
    for (int i = threadIdx.x; i < 1024; i += 256) {
        s  += part[(size_t)c*1024 + i];
        s2 += part[(size_t)C*1024 + (size_t)c*1024 + i];
    }
    rs[threadIdx.x] = s; rs2[threadIdx.x] = s2;
    __syncthreads();
    for (int o = 128; o > 0; o >>= 1) {
        if (threadIdx.x < o) {
            rs[threadIdx.x]  += rs[threadIdx.x + o];
            rs2[threadIdx.x] += rs2[threadIdx.x + o];
        }
        __syncthreads();
    }
    if (threadIdx.x == 0) {
        const float cnt = (float)NB * 4096.f;
        float mu  = rs[0] / cnt;
        float var = rs2[0] / cnt - mu*mu;
        float sc  = g[c] * rsqrtf(var + 1e-5f);
        scale[c] = sc;
        shift[c] = be[c] - mu*sc;
    }
}

// ---------------- bn2 apply + pointwise(ds) + pwblur residual --------------
__global__ __launch_bounds__(128) void bn2pw_k(
    float* __restrict__ r2, const float* __restrict__ pwblur,
    const float* __restrict__ ds, const float* __restrict__ pw,
    const float* __restrict__ pb, const float* __restrict__ scale,
    const float* __restrict__ shift)
{
    __shared__ float sw[32*20];
    __shared__ float sb[20], ssc[20], ssh[20];
    for (int i = threadIdx.x; i < 32*20; i += blockDim.x) {
        int co = i % 20, ci = i / 20;
        sw[i] = pw[co*48 + 16 + ci];
    }
    if (threadIdx.x < 20) {
        sb[threadIdx.x]  = pb[threadIdx.x];
        ssc[threadIdx.x] = scale[threadIdx.x];
        ssh[threadIdx.x] = shift[threadIdx.x];
    }
    __syncthreads();

    int idx = blockIdx.x*blockDim.x + threadIdx.x;
    if (idx >= NB*4096) return;
    int p = idx & 4095; int n = idx >> 12;

    u64 acc[10];
    const float* pbl = &pwblur[n*20];
    #pragma unroll
    for (int j = 0; j < 10; j++)
        acc[j] = pack2(sb[2*j] + pbl[2*j], sb[2*j+1] + pbl[2*j+1]);

    const float* dsp = ds + (size_t)n*32*4096 + p;
    #pragma unroll 1
    for (int ci = 0; ci < 32; ci++) {
        u64 v = bcast2(__ldg(&dsp[(size_t)ci*4096]));
        const float* wpp = &sw[ci*20];
        #pragma unroll
        for (int j = 0; j < 10; j += 2) {
            ulonglong2 wq = *reinterpret_cast<const ulonglong2*>(wpp + 2*j);
            fma2(acc[j],   v, wq.x);
            fma2(acc[j+1], v, wq.y);
        }
    }
    float* rp = r2 + (size_t)n*20*4096 + p;
    #pragma unroll
    for (int j = 0; j < 10; j++) {
        float2 a = unpack2(acc[j]);
        int c = 2*j;
        rp[(size_t)c    *4096] = fmaf(rp[(size_t)c    *4096], ssc[c],   ssh[c])   + a.x;
        rp[(size_t)(c+1)*4096] = fmaf(rp[(size_t)(c+1)*4096], ssc[c+1], ssh[c+1]) + a.y;
    }
}

// ---------------- final: u2 1x1 + relu + pixel_shuffle(4) + sigmoid --------
__global__ __launch_bounds__(128) void final_k(
    const float* __restrict__ u1, const float* __restrict__ w,
    const float* __restrict__ b, float* __restrict__ out)
{
    __shared__ float sw[30*16];
    __shared__ float sb[16];
    for (int i = threadIdx.x; i < 30*16; i += blockDim.x) {
        int co = i % 16, ci = i / 16;
        sw[i] = w[co*30 + ci];
    }
    if (threadIdx.x < 16) sb[threadIdx.x] = b[threadIdx.x];
    __syncthreads();

    int idx = blockIdx.x*blockDim.x + threadIdx.x;
    if (idx >= NB*4096) return;
    int wq = idx & 63; int h = (idx >> 6) & 63; int n = idx >> 12;

    u64 acc[8];
    #pragma unroll
    for (int j = 0; j < 8; j++) acc[j] = pack2(sb[2*j], sb[2*j+1]);

    const float* up = u1 + (size_t)n*30*4096 + h*64 + wq;
    #pragma unroll 1
    for (int ci = 0; ci < 30; ci++) {
        u64 v = bcast2(__ldg(&up[(size_t)ci*4096]));
        const float* wpp = &sw[ci*16];
        #pragma unroll
        for (int j = 0; j < 8; j += 2) {
            ulonglong2 wqv = *reinterpret_cast<const ulonglong2*>(wpp + 2*j);
            fma2(acc[j],   v, wqv.x);
            fma2(acc[j+1], v, wqv.y);
        }
    }
    float* op = out + (size_t)n*65536;
    #pragma unroll
    for (int j = 0; j < 8; j++) {
        float2 a = unpack2(acc[j]);
        #pragma unroll
        for (int h2 = 0; h2 < 2; h2++) {
            int c = 2*j + h2;
            float v = fmaxf(h2 ? a.y : a.x, 0.f);
            v = 1.f / (1.f + expf(-v));
            op[(h*4 + (c >> 2))*256 + wq*4 + (c & 3)] = v;
        }
    }
}

// ---------------------------------------------------------------------------
extern "C" void kernel_launch(void* const* d_in, const int* in_sizes, int n_in,
                              void* d_out, int out_size)
{
    const float* x1  = (const float*)d_in[0];
    const float* c1w = (const float*)d_in[1];  const float* c1b = (const float*)d_in[2];
    const float* c2w = (const float*)d_in[3];  const float* c2b = (const float*)d_in[4];
    const float* c3w = (const float*)d_in[5];  const float* c3b = (const float*)d_in[6];
    const float* c4w = (const float*)d_in[7];  const float* c4b = (const float*)d_in[8];
    const float* c5w = (const float*)d_in[9];  const float* c5b = (const float*)d_in[10];
    const float* c6w = (const float*)d_in[11]; const float* c6b = (const float*)d_in[12];
    const float* c7w = (const float*)d_in[13]; const float* c7b = (const float*)d_in[14];
    const float* r1w = (const float*)d_in[15]; const float* r1b = (const float*)d_in[16];
    const float* g1  = (const float*)d_in[17]; const float* be1 = (const float*)d_in[18];
    const float* r2w = (const float*)d_in[19]; const float* r2b = (const float*)d_in[20];
    const float* g2  = (const float*)d_in[21]; const float* be2 = (const float*)d_in[22];
    const float* pw  = (const float*)d_in[23]; const float* pb  = (const float*)d_in[24];
    const float* u1w = (const float*)d_in[25]; const float* u1b = (const float*)d_in[26];
    const float* u2w = (const float*)d_in[27]; const float* u2b = (const float*)d_in[28];

    float *t1,*ds,*t3,*r1,*r2,*u1,*part,*scale,*shift,*contrib,*pwblur;
    cudaGetSymbolAddress((void**)&t1,     g_t1);
    cudaGetSymbolAddress((void**)&ds,     g_ds);
    cudaGetSymbolAddress((void**)&t3,     g_t3);
    cudaGetSymbolAddress((void**)&r1,     g_r1);
    cudaGetSymbolAddress((void**)&r2,     g_r2);
    cudaGetSymbolAddress((void**)&u1,     g_u1);
    cudaGetSymbolAddress((void**)&part,   g_part);
    cudaGetSymbolAddress((void**)&scale,  g_scale);
    cudaGetSymbolAddress((void**)&shift,  g_shift);
    cudaGetSymbolAddress((void**)&contrib,g_contrib);
    cudaGetSymbolAddress((void**)&pwblur, g_pwblur);

    u64 *wp_r1, *wp_r2, *wp_u1, *wp_c2, *wp_c1, *wp_c3;
    cudaGetSymbolAddress((void**)&wp_r1, g_wp_r1);
    cudaGetSymbolAddress((void**)&wp_r2, g_wp_r2);
    cudaGetSymbolAddress((void**)&wp_u1, g_wp_u1);
    cudaGetSymbolAddress((void**)&wp_c2, g_wp_c2);
    cudaGetSymbolAddress((void**)&wp_c1, g_wp_c1);
    cudaGetSymbolAddress((void**)&wp_c3, g_wp_c3);

    auto smemTC = [](int cinc, int coutp, int kp, int kcp) {
        size_t in_s = (size_t)((cinc*10*68 + 3) & ~3);
        return in_s*4 + (size_t)coutp*pad64(kp/2)*8
             + (size_t)(kcp/8)*4*8 + (size_t)32*coutp*2*4;
    };
    size_t sm_r1 = smemTC(16, 64, 2*ceil8i(16*9), ceil8i(16*9));
    size_t sm_r2 = smemTC(16, 24, 4*ceil8i(16*9), ceil8i(16*9));
    size_t sm_u1 = smemTC(20, 32, 1*ceil8i(20*9), ceil8i(20*9));
    size_t sm_c2 = (size_t)(8*11*132)*4 + (size_t)32*100*8 + 100*8;
    size_t sm_c1 = (size_t)1292*4 + (size_t)8*20*8 + 8*8;
    size_t sm_c3 = (size_t)(((8*17*66 + 3) & ~3))*4 + (size_t)8*148*8 + 36*8;
    size_t sm_tail = (size_t)30240*4;

    cudaFuncSetAttribute((const void*)tc_conv3_k<32,16,48,16,64,64,false,false,true,true>,
                         cudaFuncAttributeMaxDynamicSharedMemorySize, (int)sm_r1);
    cudaFuncSetAttribute((const void*)tc_conv3_k<64,16,64,0,20,24,false,true,false,true>,
                         cudaFuncAttributeMaxDynamicSharedMemorySize, (int)sm_r2);
    cudaFuncSetAttribute((const void*)tc_conv3_k<20,20,20,0,30,32,true,false,false,false>,
                         cudaFuncAttributeMaxDynamicSharedMemorySize, (int)sm_u1);
    cudaFuncSetAttribute((const void*)tc_conv2_k,
                         cudaFuncAttributeMaxDynamicSharedMemorySize, (int)sm_c2);
    cudaFuncSetAttribute((const void*)tc_conv3s2_k,
                         cudaFuncAttributeMaxDynamicSharedMemorySize, (int)sm_c3);
    cudaFuncSetAttribute((const void*)tail_k,
                         cudaFuncAttributeMaxDynamicSharedMemorySize, (int)sm_tail);

    // ---------------- merged weight pre-pack -------------
    {
        int total = 64*148 + 24*292 + 2*32*100 + 8*20 + 8*148;
        packall_k<<<(total+127)/128,128>>>(r1w, r2w, u1w, c2w, c1w, c3w,
                                           wp_r1, wp_r2, wp_u1, wp_c2, wp_c1, wp_c3);
    }

    // ---------------- encoder ----------------
    tc_conv1_k<<<dim3(64,NB),512, sm_c1>>>(x1, wp_c1, c1b, t1);
    tc_conv2_k<<<dim3(16,NB),512, sm_c2>>>(t1, wp_c2, c2b, ds);
    tc_conv3s2_k<<<dim3(4,NB),512, sm_c3>>>(ds, wp_c3, c3b, t3);
    tail_k<<<NB,256, sm_tail>>>(t3, c4w, c4b, c5w, c5b, c6w, c6b, c7w, c7b,
                                r1w, pw, contrib, pwblur);

    // ---------------- residual block with training-mode BN ----------------
    tc_conv3_k<32,16,48,16,64,64,false,false,true,true>
        <<<dim3(8,NB),1024, sm_r1>>>(ds, wp_r1, r1b, nullptr, nullptr, contrib, r1, part);
    bn_fin2_k<64><<<64,256>>>(part, g1, be1, scale, shift);

    tc_conv3_k<64,16,64,0,20,24,false,true,false,true>
        <<<dim3(8,NB),1024, sm_r2>>>(r1, wp_r2, r2b, scale, shift, nullptr, r2, part);
    bn_fin2_k<20><<<20,256>>>(part, g2, be2, scale, shift);
    bn2pw_k<<<(NB*4096+127)/128,128>>>(r2, pwblur, ds, pw, pb, scale, shift);

    // ---------------- upsample head ----------------
    tc_conv3_k<20,20,20,0,30,32,true,false,false,false>
        <<<dim3(8,NB),1024, sm_u1>>>(r2, wp_u1, u1b, nullptr, nullptr, nullptr, u1, nullptr);
    final_k<<<(NB*4096+127)/128,128>>>(u1, u2w, u2b, (float*)d_out);
}